// round 12
// baseline (speedup 1.0000x reference)
#include <cuda_runtime.h>
#include <cuda_fp16.h>
#include <math.h>
#include <stdint.h>

#define BB 32
#define TT 2048
#define EE 1024
#define MTOT (BB * TT)   // 65536

// lo-parts are scaled by 2^11 (A: in-kernel convert; B: splitW); undone in epilogue
#define LO_SCALE 2048.0f
#define LO_INV   (1.0f / 2048.0f)

// ---------------- device scratch ----------------
__device__ __half g_ht[(size_t)MTOT * EE];        // 128 MB, tanh(enc@W+b) fp16
__device__ float g_scores[MTOT];
__device__ float g_at[MTOT];
__device__ __half g_Bhi[(size_t)EE * EE];         // Wt hi (N,K)
__device__ __half g_Blo[(size_t)EE * EE];         // Wt lo (N,K) (x 2^11)

// ---------------- helpers ----------------
__device__ __forceinline__ uint32_t smem_u32(const void* p) {
    uint32_t a;
    asm("{ .reg .u64 t; cvta.to.shared.u64 t, %1; cvt.u32.u64 %0, t; }"
        : "=r"(a) : "l"(p));
    return a;
}

__device__ __forceinline__ void cpasync16(uint32_t smem_dst, const void* gptr) {
    asm volatile("cp.async.cg.shared.global [%0], [%1], 16;"
                 :: "r"(smem_dst), "l"(gptr) : "memory");
}

__device__ __forceinline__ void ldsm4(uint32_t* r, uint32_t addr) {
    asm volatile("ldmatrix.sync.aligned.m8n8.x4.shared.b16 {%0,%1,%2,%3}, [%4];"
                 : "=r"(r[0]), "=r"(r[1]), "=r"(r[2]), "=r"(r[3]) : "r"(addr));
}

__device__ __forceinline__ float4 lds128f(uint32_t addr) {
    float4 v;
    asm volatile("ld.shared.v4.f32 {%0,%1,%2,%3}, [%4];"
                 : "=f"(v.x), "=f"(v.y), "=f"(v.z), "=f"(v.w) : "r"(addr));
    return v;
}

__device__ __forceinline__ void sts128(uint32_t addr, uint32_t a, uint32_t b,
                                       uint32_t c, uint32_t d) {
    asm volatile("st.shared.v4.b32 [%0], {%1,%2,%3,%4};"
                 :: "r"(addr), "r"(a), "r"(b), "r"(c), "r"(d) : "memory");
}

// fp32-accumulator fp16 MMA (main term)
__device__ __forceinline__ void mma16816(float* c, const uint32_t* a, const uint32_t* b) {
    asm volatile("mma.sync.aligned.m16n8k16.row.col.f32.f16.f16.f32 "
                 "{%0,%1,%2,%3}, {%4,%5,%6,%7}, {%8,%9}, {%0,%1,%2,%3};"
                 : "+f"(c[0]), "+f"(c[1]), "+f"(c[2]), "+f"(c[3])
                 : "r"(a[0]), "r"(a[1]), "r"(a[2]), "r"(a[3]),
                   "r"(b[0]), "r"(b[1]));
}

// fp16-accumulator fp16 MMA (correction terms)
__device__ __forceinline__ void mma16816h(uint32_t* c, const uint32_t* a, const uint32_t* b) {
    asm volatile("mma.sync.aligned.m16n8k16.row.col.f16.f16.f16.f16 "
                 "{%0,%1}, {%2,%3,%4,%5}, {%6,%7}, {%0,%1};"
                 : "+r"(c[0]), "+r"(c[1])
                 : "r"(a[0]), "r"(a[1]), "r"(a[2]), "r"(a[3]),
                   "r"(b[0]), "r"(b[1]));
}

// pack two floats -> fp16x2 {lo=x, hi=y}
__device__ __forceinline__ uint32_t packh2(float x, float y) {
    __half2 h = __floats2half2_rn(x, y);
    return *(uint32_t*)&h;
}

// ---------------- GEMM config ----------------
#define MT 128
#define NT 64
#define BK 64                                   // k elems per chunk
#define NCHUNK (EE / BK)                        // 16
// A area: 128 rows x 256 B (fp32 raw, converted IN PLACE to hi/lo fp16 blocks)
//   per-row layout after convert: 4 blocks of 64B, block b (k=16b..16b+15):
//   granule 4b+0: hi halves 0-7, 4b+1: hi 8-15, 4b+2: lo 0-7, 4b+3: lo 8-15
//   granule addresses swizzled: (g ^ (r & 15)) within the 256B row
#define OFF_A 0
#define OFF_BHI (MT * BK * 4)                   // 32768 (B: 64 rows x 128B)
#define OFF_BLO (MT * BK * 4 + NT * BK * 2)     // 40960
#define STAGE_BYTES (MT * BK * 4 + 2 * NT * BK * 2)  // 49152
#define DSM_BYTES (2 * STAGE_BYTES)             // 98304 per CTA (2 CTAs/SM)

// ---------------- prepass: transpose + split W -> Wt[n][k] fp16 hi + scaled lo ----------------
__global__ void __launch_bounds__(256) splitW_kernel(const float* __restrict__ W)
{
    __shared__ float tile[32][33];
    int n0 = blockIdx.x * 32, k0 = blockIdx.y * 32;
    int tx = threadIdx.x & 31, ty = threadIdx.x >> 5;  // 32 x 8
#pragma unroll
    for (int r = 0; r < 4; r++)
        tile[ty + 8 * r][tx] = W[(size_t)(k0 + ty + 8 * r) * EE + n0 + tx];
    __syncthreads();
#pragma unroll
    for (int r = 0; r < 4; r++) {
        int ny = ty + 8 * r;
        float v = tile[tx][ny];
        __half h = __float2half_rn(v);
        __half l = __float2half_rn((v - __half2float(h)) * LO_SCALE);
        size_t o = (size_t)(n0 + ny) * EE + k0 + tx;
        g_Bhi[o] = h;
        g_Blo[o] = l;
    }
}

__global__ void __launch_bounds__(256) zero_scores_kernel()
{
    g_scores[blockIdx.x * 256 + threadIdx.x] = 0.0f;
}

// ---------------- fused GEMM (+fp32->hi/lo convert) + bias + tanh + scores ----------------
// A raw fp32 granule address within a 256B row, swizzled
__device__ __forceinline__ uint32_t a_gran(uint32_t base, int r, int g) {
    return base + (uint32_t)(r * 256 + ((g ^ (r & 15)) << 4));
}
// B 128B rows, XOR-16B swizzle (as R9)
__device__ __forceinline__ uint32_t b_frag_addr(uint32_t base, int n0, int t, int lane) {
    int r = n0 + (lane & 7) + ((lane & 16) >> 1);
    int j = t * 2 + ((lane >> 3) & 1);
    return base + (uint32_t)(r * 128 + ((j ^ (r & 7)) << 4));
}
// A hi fragment: block t, hi granules 4t + {0,1}
__device__ __forceinline__ uint32_t a_hi_addr(uint32_t base, int row0, int t, int lane) {
    int r = row0 + (lane & 15);
    int g = 4 * t + (lane >> 4);
    return a_gran(base, r, g);
}
// A lo fragment: block t, lo granules 4t + {2,3}
__device__ __forceinline__ uint32_t a_lo_addr(uint32_t base, int row0, int t, int lane) {
    int r = row0 + (lane & 15);
    int g = 4 * t + 2 + (lane >> 4);
    return a_gran(base, r, g);
}

__device__ __forceinline__ void load_chunk(int c, uint32_t sm0,
                                           const float* __restrict__ enc,
                                           size_t m0, int n0, int tid)
{
    uint32_t sb = sm0 + (uint32_t)(c & 1) * STAGE_BYTES;
    int k0 = c * BK;
    const float* Ap = enc + m0 * EE + k0;
    const __half* Bhi = g_Bhi + (size_t)n0 * EE + k0;
    const __half* Blo = g_Blo + (size_t)n0 * EE + k0;
#pragma unroll
    for (int i = 0; i < 8; i++) {           // A raw fp32: 128 rows x 16 granules(16B)
        int idx = tid + i * 256;
        int row = idx >> 4, g = idx & 15;
        cpasync16(a_gran(sb + OFF_A, row, g), Ap + (size_t)row * EE + 4 * g);
    }
#pragma unroll
    for (int i = 0; i < 2; i++) {           // B: 64 rows x 8 granules(16B)
        int idx = tid + i * 256;
        int row = idx >> 3, j = idx & 7;
        uint32_t d = sb + (uint32_t)(row * 128 + ((j ^ (row & 7)) << 4));
        const size_t go = (size_t)row * EE + j * 8;
        cpasync16(d + OFF_BHI, Bhi + go);
        cpasync16(d + OFF_BLO, Blo + go);
    }
    asm volatile("cp.async.commit_group;" ::: "memory");
}

// convert one 64B block (16 floats) in place: reads granules 4b..4b+3 of row r,
// writes hi to 4b,4b+1 and scaled lo to 4b+2,4b+3 (same granules it read).
__device__ __forceinline__ void convert_block(uint32_t sA, int r, int b)
{
    uint32_t a0 = a_gran(sA, r, 4 * b + 0);
    uint32_t a1 = a_gran(sA, r, 4 * b + 1);
    uint32_t a2 = a_gran(sA, r, 4 * b + 2);
    uint32_t a3 = a_gran(sA, r, 4 * b + 3);
    float4 f0 = lds128f(a0);
    float4 f1 = lds128f(a1);
    float4 f2 = lds128f(a2);
    float4 f3 = lds128f(a3);

    uint32_t h0 = packh2(f0.x, f0.y), h1 = packh2(f0.z, f0.w);
    uint32_t h2 = packh2(f1.x, f1.y), h3 = packh2(f1.z, f1.w);
    uint32_t h4 = packh2(f2.x, f2.y), h5 = packh2(f2.z, f2.w);
    uint32_t h6 = packh2(f3.x, f3.y), h7 = packh2(f3.z, f3.w);

    // residuals (scaled)
    float2 b0 = __half22float2(*(__half2*)&h0), b1 = __half22float2(*(__half2*)&h1);
    float2 b2 = __half22float2(*(__half2*)&h2), b3 = __half22float2(*(__half2*)&h3);
    float2 b4 = __half22float2(*(__half2*)&h4), b5 = __half22float2(*(__half2*)&h5);
    float2 b6 = __half22float2(*(__half2*)&h6), b7 = __half22float2(*(__half2*)&h7);
    uint32_t l0 = packh2((f0.x - b0.x) * LO_SCALE, (f0.y - b0.y) * LO_SCALE);
    uint32_t l1 = packh2((f0.z - b1.x) * LO_SCALE, (f0.w - b1.y) * LO_SCALE);
    uint32_t l2 = packh2((f1.x - b2.x) * LO_SCALE, (f1.y - b2.y) * LO_SCALE);
    uint32_t l3 = packh2((f1.z - b3.x) * LO_SCALE, (f1.w - b3.y) * LO_SCALE);
    uint32_t l4 = packh2((f2.x - b4.x) * LO_SCALE, (f2.y - b4.y) * LO_SCALE);
    uint32_t l5 = packh2((f2.z - b5.x) * LO_SCALE, (f2.w - b5.y) * LO_SCALE);
    uint32_t l6 = packh2((f3.x - b6.x) * LO_SCALE, (f3.y - b6.y) * LO_SCALE);
    uint32_t l7 = packh2((f3.z - b7.x) * LO_SCALE, (f3.w - b7.y) * LO_SCALE);

    sts128(a0, h0, h1, h2, h3);   // hi halves 0-7
    sts128(a1, h4, h5, h6, h7);   // hi halves 8-15
    sts128(a2, l0, l1, l2, l3);   // lo halves 0-7
    sts128(a3, l4, l5, l6, l7);   // lo halves 8-15
}

__global__ void __launch_bounds__(256, 2) gemm_hmma_kernel(
    const float* __restrict__ enc,
    const float* __restrict__ ctx,
    const float* __restrict__ bias)
{
    extern __shared__ __align__(1024) char dsm_raw[];
    uint32_t sm0 = smem_u32(dsm_raw);

    __shared__ float s_bias[NT];
    __shared__ float s_ctx[NT];

    const int tid = threadIdx.x;
    const int wid = tid >> 5, lane = tid & 31;
    const int warp_m = wid & 3;              // 0..3 (32-row slabs)
    const int warp_n = wid >> 2;             // 0..1 (32-col slabs)
    const int n0c = blockIdx.x * NT;
    const size_t m0 = (size_t)blockIdx.y * MT;
    const int bidx = (int)(m0 / TT);

    if (tid < NT) {
        s_bias[tid] = bias[n0c + tid];
        s_ctx[tid]  = ctx[bidx * EE + n0c + tid];
    }

    float acc[2][4][4];                      // main term, fp32
    uint32_t ach[2][4][2];                   // correction terms, fp16x2 (x 2^11)
#pragma unroll
    for (int mi = 0; mi < 2; mi++)
#pragma unroll
        for (int ni = 0; ni < 4; ni++) {
#pragma unroll
            for (int e = 0; e < 4; e++) acc[mi][ni][e] = 0.0f;
            ach[mi][ni][0] = 0u;
            ach[mi][ni][1] = 0u;
        }

    load_chunk(0, sm0, enc, m0, n0c, tid);

    for (int c = 0; c < NCHUNK; c++) {
        asm volatile("cp.async.wait_group 0;" ::: "memory");
        __syncthreads();

        const uint32_t sb = sm0 + (uint32_t)(c & 1) * STAGE_BYTES;
        const uint32_t sA = sb + OFF_A;

        // convert A raw fp32 -> hi/lo fp16, in place (each thread owns its blocks)
        {
            int task = tid;                  // 128 rows x 4 blocks = 512 tasks
            convert_block(sA, task >> 2, task & 3);
            task = tid + 256;
            convert_block(sA, task >> 2, task & 3);
        }
        __syncthreads();

        // prefetch next chunk into the other buffer (its reads finished last iter)
        if (c + 1 < NCHUNK) load_chunk(c + 1, sm0, enc, m0, n0c, tid);

        const uint32_t sBhi = sb + OFF_BHI;
        const uint32_t sBlo = sb + OFF_BLO;

#pragma unroll
        for (int t = 0; t < 4; t++) {       // 4 k16 steps per BK=64
            uint32_t bh[2][4], bl[2][4], af[2][4], al[2][4];
#pragma unroll
            for (int np = 0; np < 2; np++) {
                ldsm4(bh[np], b_frag_addr(sBhi, warp_n * 32 + np * 16, t, lane));
                ldsm4(bl[np], b_frag_addr(sBlo, warp_n * 32 + np * 16, t, lane));
            }
#pragma unroll
            for (int mi = 0; mi < 2; mi++) {
                ldsm4(af[mi], a_hi_addr(sA, warp_m * 32 + mi * 16, t, lane));
                ldsm4(al[mi], a_lo_addr(sA, warp_m * 32 + mi * 16, t, lane));
            }
#pragma unroll
            for (int mi = 0; mi < 2; mi++)
#pragma unroll
                for (int ni = 0; ni < 4; ni++) {
                    mma16816(acc[mi][ni], af[mi], &bh[ni >> 1][(ni & 1) * 2]);
                    mma16816h(ach[mi][ni], af[mi], &bl[ni >> 1][(ni & 1) * 2]);
                    mma16816h(ach[mi][ni], al[mi], &bh[ni >> 1][(ni & 1) * 2]);
                }
        }
    }

    // epilogue: main + 2^-11 * corrections + bias, tanh, fp16 ht store, fused scores
    const int lr = lane >> 2;               // 0..7
    const int lc = (lane & 3) * 2;
    const int tbase = (int)(m0 % TT) + warp_m * 32;
#pragma unroll
    for (int mi = 0; mi < 2; mi++) {
        const size_t row0 = m0 + (size_t)(warp_m * 32 + mi * 16 + lr);
        float rs0 = 0.0f, rs1 = 0.0f;
#pragma unroll
        for (int ni = 0; ni < 4; ni++) {
            const int col = warp_n * 32 + ni * 8 + lc;
            const float b0 = s_bias[col], b1 = s_bias[col + 1];
            const float c0 = s_ctx[col],  c1 = s_ctx[col + 1];
            float2 cr0 = __half22float2(*(__half2*)&ach[mi][ni][0]);
            float2 cr1 = __half22float2(*(__half2*)&ach[mi][ni][1]);
            float2 v0, v1;
            v0.x = tanhf(acc[mi][ni][0] + LO_INV * cr0.x + b0);
            v0.y = tanhf(acc[mi][ni][1] + LO_INV * cr0.y + b1);
            v1.x = tanhf(acc[mi][ni][2] + LO_INV * cr1.x + b0);
            v1.y = tanhf(acc[mi][ni][3] + LO_INV * cr1.y + b1);
            *(__half2*)(g_ht + row0 * EE + n0c + col) = __float22half2_rn(v0);
            *(__half2*)(g_ht + (row0 + 8) * EE + n0c + col) = __float22half2_rn(v1);
            rs0 += v0.x * c0 + v0.y * c1;
            rs1 += v1.x * c0 + v1.y * c1;
        }
        rs0 += __shfl_xor_sync(0xffffffffu, rs0, 1);
        rs0 += __shfl_xor_sync(0xffffffffu, rs0, 2);
        rs1 += __shfl_xor_sync(0xffffffffu, rs1, 1);
        rs1 += __shfl_xor_sync(0xffffffffu, rs1, 2);
        if ((lane & 3) == 0) {
            atomicAdd(&g_scores[bidx * TT + tbase + mi * 16 + lr], rs0);
            atomicAdd(&g_scores[bidx * TT + tbase + mi * 16 + lr + 8], rs1);
        }
    }
}

// ---------------- softmax / pool ----------------
__global__ void __launch_bounds__(256) softmax_kernel()
{
    __shared__ float red[256];
    const int b = blockIdx.x;
    const int tid = threadIdx.x;

    float v[8];
    float m = -1e30f;
#pragma unroll
    for (int i = 0; i < 8; i++) {
        v[i] = g_scores[b * TT + tid + i * 256];
        m = fmaxf(m, v[i]);
    }
    red[tid] = m;
    __syncthreads();
#pragma unroll
    for (int s = 128; s > 0; s >>= 1) {
        if (tid < s) red[tid] = fmaxf(red[tid], red[tid + s]);
        __syncthreads();
    }
    const float mx = red[0];
    __syncthreads();

    float sum = 0.0f;
#pragma unroll
    for (int i = 0; i < 8; i++) {
        v[i] = expf(v[i] - mx);
        sum += v[i];
    }
    red[tid] = sum;
    __syncthreads();
#pragma unroll
    for (int s = 128; s > 0; s >>= 1) {
        if (tid < s) red[tid] += red[tid + s];
        __syncthreads();
    }
    const float inv = 1.0f / red[0];
#pragma unroll
    for (int i = 0; i < 8; i++)
        g_at[b * TT + tid + i * 256] = v[i] * inv;
}

// out[b][e0..e0+1] += sum_t at * ht ; ht fp16, 2 cols per thread
__global__ void __launch_bounds__(256) pool_kernel(float* __restrict__ out)
{
    __shared__ float ats[256];
    const int b = blockIdx.z;
    const int e = (blockIdx.x * 256 + threadIdx.x) * 2;
    const int t0 = blockIdx.y * 256;

    ats[threadIdx.x] = g_at[b * TT + t0 + threadIdx.x];
    __syncthreads();

    const __half2* hp = (const __half2*)(g_ht + ((size_t)(b * TT + t0)) * EE + e);
    float ax = 0.0f, ay = 0.0f;
#pragma unroll 8
    for (int i = 0; i < 256; i++) {
        float2 h = __half22float2(hp[(size_t)i * (EE / 2)]);
        ax += ats[i] * h.x;
        ay += ats[i] * h.y;
    }
    atomicAdd(&out[b * EE + e], ax);
    atomicAdd(&out[b * EE + e + 1], ay);
}

// ---------------- launch ----------------
extern "C" void kernel_launch(void* const* d_in, const int* in_sizes, int n_in,
                              void* d_out, int out_size)
{
    const float* enc  = (const float*)d_in[0];   // (B, T, E)
    const float* ctx  = (const float*)d_in[1];   // (B, E)
    const float* Wm   = (const float*)d_in[2];   // (E, E)
    const float* bias = (const float*)d_in[3];   // (1, E)
    float* out = (float*)d_out;                  // (B, E)

    cudaFuncSetAttribute(gemm_hmma_kernel,
                         cudaFuncAttributeMaxDynamicSharedMemorySize, DSM_BYTES);

    cudaMemsetAsync(out, 0, sizeof(float) * BB * EE);

    zero_scores_kernel<<<MTOT / 256, 256>>>();
    splitW_kernel<<<dim3(EE / 32, EE / 32), 256>>>(Wm);
    gemm_hmma_kernel<<<dim3(EE / NT, MTOT / MT), 256, DSM_BYTES>>>(enc, ctx, bias);
    softmax_kernel<<<BB, 256>>>();
    pool_kernel<<<dim3(EE / 512, TT / 256, BB), 256>>>(out);
}

// round 13
// speedup vs baseline: 1.2447x; 1.2447x over previous
#include <cuda_runtime.h>
#include <cuda_fp16.h>
#include <math.h>
#include <stdint.h>

#define BB 32
#define TT 2048
#define EE 1024
#define MTOT (BB * TT)   // 65536

// lo-parts are pre-scaled by 2^11 at split time; undone in the epilogue
#define LO_SCALE 2048.0f
#define LO_INV   (1.0f / 2048.0f)

// ---------------- device scratch ----------------
__device__ __half g_ht[(size_t)MTOT * EE];        // 128 MB, tanh(enc@W+b) fp16
__device__ float g_scores[MTOT];
__device__ float g_at[MTOT];
__device__ __half g_Ahi[(size_t)MTOT * EE];       // 128 MB
__device__ __half g_Alo[(size_t)MTOT * EE];       // 128 MB (x 2^11)
__device__ __half g_Bhi[(size_t)EE * EE];         // Wt hi (N,K)
__device__ __half g_Blo[(size_t)EE * EE];         // Wt lo (N,K) (x 2^11)

// ---------------- helpers ----------------
__device__ __forceinline__ uint32_t smem_u32(const void* p) {
    uint32_t a;
    asm("{ .reg .u64 t; cvta.to.shared.u64 t, %1; cvt.u32.u64 %0, t; }"
        : "=r"(a) : "l"(p));
    return a;
}

__device__ __forceinline__ void cpasync16(uint32_t smem_dst, const void* gptr) {
    asm volatile("cp.async.cg.shared.global [%0], [%1], 16;"
                 :: "r"(smem_dst), "l"(gptr) : "memory");
}

__device__ __forceinline__ void ldsm4(uint32_t* r, uint32_t addr) {
    asm volatile("ldmatrix.sync.aligned.m8n8.x4.shared.b16 {%0,%1,%2,%3}, [%4];"
                 : "=r"(r[0]), "=r"(r[1]), "=r"(r[2]), "=r"(r[3]) : "r"(addr));
}

// fp32-accumulator fp16 MMA (main term)
__device__ __forceinline__ void mma16816(float* c, const uint32_t* a, const uint32_t* b) {
    asm volatile("mma.sync.aligned.m16n8k16.row.col.f32.f16.f16.f32 "
                 "{%0,%1,%2,%3}, {%4,%5,%6,%7}, {%8,%9}, {%0,%1,%2,%3};"
                 : "+f"(c[0]), "+f"(c[1]), "+f"(c[2]), "+f"(c[3])
                 : "r"(a[0]), "r"(a[1]), "r"(a[2]), "r"(a[3]),
                   "r"(b[0]), "r"(b[1]));
}

// fp16-accumulator fp16 MMA (correction terms)
__device__ __forceinline__ void mma16816h(uint32_t* c, const uint32_t* a, const uint32_t* b) {
    asm volatile("mma.sync.aligned.m16n8k16.row.col.f16.f16.f16.f16 "
                 "{%0,%1}, {%2,%3,%4,%5}, {%6,%7}, {%0,%1};"
                 : "+r"(c[0]), "+r"(c[1])
                 : "r"(a[0]), "r"(a[1]), "r"(a[2]), "r"(a[3]),
                   "r"(b[0]), "r"(b[1]));
}

// ---------------- GEMM config ----------------
#define MT 64
#define NT 64
#define BK 64                                   // k elems per chunk (128 B rows)
#define NCHUNK (EE / BK)                        // 16
#define OFF_AHI 0
#define OFF_ALO (MT * BK * 2)                   // 8192
#define OFF_BHI (2 * MT * BK * 2)               // 16384
#define OFF_BLO (2 * MT * BK * 2 + NT * BK * 2) // 24576
#define STAGE_BYTES (2 * MT * BK * 2 + 2 * NT * BK * 2)  // 32768
#define DSM_BYTES (2 * STAGE_BYTES)             // 65536 per CTA (3 CTAs/SM)

// ---------------- prepass: split enc into fp16 hi + scaled lo ----------------
__global__ void __launch_bounds__(256) split_enc_kernel(const float* __restrict__ A)
{
    size_t i = ((size_t)blockIdx.x * 256 + threadIdx.x) * 4;
    float4 v = *(const float4*)(A + i);
    __half h0 = __float2half_rn(v.x);
    __half h1 = __float2half_rn(v.y);
    __half h2 = __float2half_rn(v.z);
    __half h3 = __float2half_rn(v.w);
    __half l0 = __float2half_rn((v.x - __half2float(h0)) * LO_SCALE);
    __half l1 = __float2half_rn((v.y - __half2float(h1)) * LO_SCALE);
    __half l2 = __float2half_rn((v.z - __half2float(h2)) * LO_SCALE);
    __half l3 = __float2half_rn((v.w - __half2float(h3)) * LO_SCALE);
    __half2 hp0 = __halves2half2(h0, h1);
    __half2 hp1 = __halves2half2(h2, h3);
    __half2 lp0 = __halves2half2(l0, l1);
    __half2 lp1 = __halves2half2(l2, l3);
    *(uint2*)(g_Ahi + i) = make_uint2(*(uint32_t*)&hp0, *(uint32_t*)&hp1);
    *(uint2*)(g_Alo + i) = make_uint2(*(uint32_t*)&lp0, *(uint32_t*)&lp1);
}

// ---------------- prepass: transpose + split W -> Wt[n][k] fp16 hi + scaled lo ----------------
__global__ void __launch_bounds__(256) splitW_kernel(const float* __restrict__ W)
{
    __shared__ float tile[32][33];
    int n0 = blockIdx.x * 32, k0 = blockIdx.y * 32;
    int tx = threadIdx.x & 31, ty = threadIdx.x >> 5;  // 32 x 8
#pragma unroll
    for (int r = 0; r < 4; r++)
        tile[ty + 8 * r][tx] = W[(size_t)(k0 + ty + 8 * r) * EE + n0 + tx];
    __syncthreads();
#pragma unroll
    for (int r = 0; r < 4; r++) {
        int ny = ty + 8 * r;
        float v = tile[tx][ny];
        __half h = __float2half_rn(v);
        __half l = __float2half_rn((v - __half2float(h)) * LO_SCALE);
        size_t o = (size_t)(n0 + ny) * EE + k0 + tx;
        g_Bhi[o] = h;
        g_Blo[o] = l;
    }
}

__global__ void __launch_bounds__(256) zero_scores_kernel()
{
    g_scores[blockIdx.x * 256 + threadIdx.x] = 0.0f;
}

// ---------------- fused GEMM + bias + tanh + scores ----------------
__device__ __forceinline__ void load_chunk(int c, uint32_t sm0, size_t m0, int n0, int tid)
{
    uint32_t sb = sm0 + (uint32_t)(c & 1) * STAGE_BYTES;
    int k0 = c * BK;
    const __half* Ahi = g_Ahi + m0 * EE + k0;
    const __half* Alo = g_Alo + m0 * EE + k0;
    const __half* Bhi = g_Bhi + (size_t)n0 * EE + k0;
    const __half* Blo = g_Blo + (size_t)n0 * EE + k0;
#pragma unroll
    for (int i = 0; i < 2; i++) {           // A: 64 rows x 8 granules(16B)
        int idx = tid + i * 256;
        int row = idx >> 3, j = idx & 7;
        uint32_t d = sb + (uint32_t)(row * 128 + ((j ^ (row & 7)) << 4));
        const size_t go = (size_t)row * EE + j * 8;
        cpasync16(d + OFF_AHI, Ahi + go);
        cpasync16(d + OFF_ALO, Alo + go);
    }
#pragma unroll
    for (int i = 0; i < 2; i++) {           // B: 64 rows x 8 granules(16B)
        int idx = tid + i * 256;
        int row = idx >> 3, j = idx & 7;
        uint32_t d = sb + (uint32_t)(row * 128 + ((j ^ (row & 7)) << 4));
        const size_t go = (size_t)row * EE + j * 8;
        cpasync16(d + OFF_BHI, Bhi + go);
        cpasync16(d + OFF_BLO, Blo + go);
    }
    asm volatile("cp.async.commit_group;" ::: "memory");
}

__device__ __forceinline__ uint32_t a_frag_addr(uint32_t base, int row0, int t, int lane) {
    int r = row0 + (lane & 15);
    int j = t * 2 + (lane >> 4);
    return base + (uint32_t)(r * 128 + ((j ^ (r & 7)) << 4));
}
__device__ __forceinline__ uint32_t b_frag_addr(uint32_t base, int n0, int t, int lane) {
    int r = n0 + (lane & 7) + ((lane & 16) >> 1);
    int j = t * 2 + ((lane >> 3) & 1);
    return base + (uint32_t)(r * 128 + ((j ^ (r & 7)) << 4));
}

__global__ void __launch_bounds__(256, 3) gemm_hmma_kernel(
    const float* __restrict__ ctx,
    const float* __restrict__ bias)
{
    extern __shared__ __align__(1024) char dsm_raw[];
    uint32_t sm0 = smem_u32(dsm_raw);

    __shared__ float s_bias[NT];
    __shared__ float s_ctx[NT];

    const int tid = threadIdx.x;
    const int wid = tid >> 5, lane = tid & 31;
    const int warp_m = wid & 3;              // 0..3 (16-row slabs)
    const int warp_n = wid >> 2;             // 0..1 (32-col slabs)
    const int n0c = blockIdx.x * NT;
    const size_t m0 = (size_t)blockIdx.y * MT;
    const int bidx = (int)(m0 / TT);

    if (tid < NT) {
        s_bias[tid] = bias[n0c + tid];
        s_ctx[tid]  = ctx[bidx * EE + n0c + tid];
    }

    float acc[4][4];                         // main term, fp32 (ni x 4)
    uint32_t ach[4][2];                      // correction terms, fp16x2 (x 2^11)
#pragma unroll
    for (int ni = 0; ni < 4; ni++) {
#pragma unroll
        for (int e = 0; e < 4; e++) acc[ni][e] = 0.0f;
        ach[ni][0] = 0u;
        ach[ni][1] = 0u;
    }

    load_chunk(0, sm0, m0, n0c, tid);

    for (int c = 0; c < NCHUNK; c++) {
        asm volatile("cp.async.wait_group 0;" ::: "memory");
        __syncthreads();
        // prefetch next chunk into the buffer everyone just finished reading
        if (c + 1 < NCHUNK) load_chunk(c + 1, sm0, m0, n0c, tid);

        const uint32_t sb   = sm0 + (uint32_t)(c & 1) * STAGE_BYTES;
        const uint32_t sAhi = sb + OFF_AHI;
        const uint32_t sAlo = sb + OFF_ALO;
        const uint32_t sBhi = sb + OFF_BHI;
        const uint32_t sBlo = sb + OFF_BLO;

#pragma unroll
        for (int t = 0; t < 4; t++) {       // 4 k16 steps per BK=64
            uint32_t bh[2][4], bl[2][4], af[4], al[4];
#pragma unroll
            for (int np = 0; np < 2; np++) {
                ldsm4(bh[np], b_frag_addr(sBhi, warp_n * 32 + np * 16, t, lane));
                ldsm4(bl[np], b_frag_addr(sBlo, warp_n * 32 + np * 16, t, lane));
            }
            ldsm4(af, a_frag_addr(sAhi, warp_m * 16, t, lane));
            ldsm4(al, a_frag_addr(sAlo, warp_m * 16, t, lane));
#pragma unroll
            for (int ni = 0; ni < 4; ni++) {
                mma16816(acc[ni], af, &bh[ni >> 1][(ni & 1) * 2]);
                mma16816h(ach[ni], af, &bl[ni >> 1][(ni & 1) * 2]);
                mma16816h(ach[ni], al, &bh[ni >> 1][(ni & 1) * 2]);
            }
        }
    }

    // epilogue: main + 2^-11 * corrections + bias, tanh, fp16 ht store, fused scores
    const int lr = lane >> 2;               // 0..7
    const int lc = (lane & 3) * 2;
    const int tbase = (int)(m0 % TT) + warp_m * 16;
    const size_t row0 = m0 + (size_t)(warp_m * 16 + lr);
    float rs0 = 0.0f, rs1 = 0.0f;
#pragma unroll
    for (int ni = 0; ni < 4; ni++) {
        const int col = warp_n * 32 + ni * 8 + lc;
        const float b0 = s_bias[col], b1 = s_bias[col + 1];
        const float c0 = s_ctx[col],  c1 = s_ctx[col + 1];
        float2 cr0 = __half22float2(*(__half2*)&ach[ni][0]);
        float2 cr1 = __half22float2(*(__half2*)&ach[ni][1]);
        float2 v0, v1;
        v0.x = tanhf(acc[ni][0] + LO_INV * cr0.x + b0);
        v0.y = tanhf(acc[ni][1] + LO_INV * cr0.y + b1);
        v1.x = tanhf(acc[ni][2] + LO_INV * cr1.x + b0);
        v1.y = tanhf(acc[ni][3] + LO_INV * cr1.y + b1);
        *(__half2*)(g_ht + row0 * EE + n0c + col) = __float22half2_rn(v0);
        *(__half2*)(g_ht + (row0 + 8) * EE + n0c + col) = __float22half2_rn(v1);
        rs0 += v0.x * c0 + v0.y * c1;
        rs1 += v1.x * c0 + v1.y * c1;
    }
    rs0 += __shfl_xor_sync(0xffffffffu, rs0, 1);
    rs0 += __shfl_xor_sync(0xffffffffu, rs0, 2);
    rs1 += __shfl_xor_sync(0xffffffffu, rs1, 1);
    rs1 += __shfl_xor_sync(0xffffffffu, rs1, 2);
    if ((lane & 3) == 0) {
        atomicAdd(&g_scores[bidx * TT + tbase + lr], rs0);
        atomicAdd(&g_scores[bidx * TT + tbase + lr + 8], rs1);
    }
}

// ---------------- softmax / pool ----------------
__global__ void __launch_bounds__(256) softmax_kernel()
{
    __shared__ float red[256];
    const int b = blockIdx.x;
    const int tid = threadIdx.x;

    float v[8];
    float m = -1e30f;
#pragma unroll
    for (int i = 0; i < 8; i++) {
        v[i] = g_scores[b * TT + tid + i * 256];
        m = fmaxf(m, v[i]);
    }
    red[tid] = m;
    __syncthreads();
#pragma unroll
    for (int s = 128; s > 0; s >>= 1) {
        if (tid < s) red[tid] = fmaxf(red[tid], red[tid + s]);
        __syncthreads();
    }
    const float mx = red[0];
    __syncthreads();

    float sum = 0.0f;
#pragma unroll
    for (int i = 0; i < 8; i++) {
        v[i] = expf(v[i] - mx);
        sum += v[i];
    }
    red[tid] = sum;
    __syncthreads();
#pragma unroll
    for (int s = 128; s > 0; s >>= 1) {
        if (tid < s) red[tid] += red[tid + s];
        __syncthreads();
    }
    const float inv = 1.0f / red[0];
#pragma unroll
    for (int i = 0; i < 8; i++)
        g_at[b * TT + tid + i * 256] = v[i] * inv;
}

// out[b][e0..e0+1] += sum_t at * ht ; ht fp16, 2 cols per thread
__global__ void __launch_bounds__(256) pool_kernel(float* __restrict__ out)
{
    __shared__ float ats[256];
    const int b = blockIdx.z;
    const int e = (blockIdx.x * 256 + threadIdx.x) * 2;
    const int t0 = blockIdx.y * 256;

    ats[threadIdx.x] = g_at[b * TT + t0 + threadIdx.x];
    __syncthreads();

    const __half2* hp = (const __half2*)(g_ht + ((size_t)(b * TT + t0)) * EE + e);
    float ax = 0.0f, ay = 0.0f;
#pragma unroll 8
    for (int i = 0; i < 256; i++) {
        float2 h = __half22float2(hp[(size_t)i * (EE / 2)]);
        ax += ats[i] * h.x;
        ay += ats[i] * h.y;
    }
    atomicAdd(&out[b * EE + e], ax);
    atomicAdd(&out[b * EE + e + 1], ay);
}

// ---------------- launch ----------------
extern "C" void kernel_launch(void* const* d_in, const int* in_sizes, int n_in,
                              void* d_out, int out_size)
{
    const float* enc  = (const float*)d_in[0];   // (B, T, E)
    const float* ctx  = (const float*)d_in[1];   // (B, E)
    const float* Wm   = (const float*)d_in[2];   // (E, E)
    const float* bias = (const float*)d_in[3];   // (1, E)
    float* out = (float*)d_out;                  // (B, E)

    cudaFuncSetAttribute(gemm_hmma_kernel,
                         cudaFuncAttributeMaxDynamicSharedMemorySize, DSM_BYTES);

    cudaMemsetAsync(out, 0, sizeof(float) * BB * EE);

    zero_scores_kernel<<<MTOT / 256, 256>>>();
    split_enc_kernel<<<(size_t)MTOT * EE / 1024, 256>>>(enc);
    splitW_kernel<<<dim3(EE / 32, EE / 32), 256>>>(Wm);
    gemm_hmma_kernel<<<dim3(EE / NT, MTOT / MT), 256, DSM_BYTES>>>(ctx, bias);
    softmax_kernel<<<BB, 256>>>();
    pool_kernel<<<dim3(EE / 512, TT / 256, BB), 256>>>(out);
}

// round 14
// speedup vs baseline: 1.3348x; 1.0725x over previous
#include <cuda_runtime.h>
#include <cuda_fp16.h>
#include <math.h>
#include <stdint.h>

#define BB 32
#define TT 2048
#define EE 1024
#define MTOT (BB * TT)   // 65536

// lo-parts are pre-scaled by 2^11 at split time; undone in the epilogue
#define LO_SCALE 2048.0f
#define LO_INV   (1.0f / 2048.0f)

// ---------------- device scratch ----------------
__device__ __half g_ht[(size_t)MTOT * EE];        // 128 MB, tanh(enc@W+b) fp16
__device__ float g_scores[MTOT];
__device__ float g_at[MTOT];
__device__ __half g_Ahi[(size_t)MTOT * EE];       // 128 MB
__device__ __half g_Alo[(size_t)MTOT * EE];       // 128 MB (x 2^11)
__device__ __half g_Bhi[(size_t)EE * EE];         // Wt hi (N,K)
__device__ __half g_Blo[(size_t)EE * EE];         // Wt lo (N,K) (x 2^11)

// ---------------- helpers ----------------
__device__ __forceinline__ uint32_t smem_u32(const void* p) {
    uint32_t a;
    asm("{ .reg .u64 t; cvta.to.shared.u64 t, %1; cvt.u32.u64 %0, t; }"
        : "=r"(a) : "l"(p));
    return a;
}

__device__ __forceinline__ void cpasync16(uint32_t smem_dst, const void* gptr) {
    asm volatile("cp.async.cg.shared.global [%0], [%1], 16;"
                 :: "r"(smem_dst), "l"(gptr) : "memory");
}

__device__ __forceinline__ void ldsm4(uint32_t* r, uint32_t addr) {
    asm volatile("ldmatrix.sync.aligned.m8n8.x4.shared.b16 {%0,%1,%2,%3}, [%4];"
                 : "=r"(r[0]), "=r"(r[1]), "=r"(r[2]), "=r"(r[3]) : "r"(addr));
}

// fp32-accumulator fp16 MMA (main term)
__device__ __forceinline__ void mma16816(float* c, const uint32_t* a, const uint32_t* b) {
    asm volatile("mma.sync.aligned.m16n8k16.row.col.f32.f16.f16.f32 "
                 "{%0,%1,%2,%3}, {%4,%5,%6,%7}, {%8,%9}, {%0,%1,%2,%3};"
                 : "+f"(c[0]), "+f"(c[1]), "+f"(c[2]), "+f"(c[3])
                 : "r"(a[0]), "r"(a[1]), "r"(a[2]), "r"(a[3]),
                   "r"(b[0]), "r"(b[1]));
}

// fp16-accumulator fp16 MMA (correction terms)
__device__ __forceinline__ void mma16816h(uint32_t* c, const uint32_t* a, const uint32_t* b) {
    asm volatile("mma.sync.aligned.m16n8k16.row.col.f16.f16.f16.f16 "
                 "{%0,%1}, {%2,%3,%4,%5}, {%6,%7}, {%0,%1};"
                 : "+r"(c[0]), "+r"(c[1])
                 : "r"(a[0]), "r"(a[1]), "r"(a[2]), "r"(a[3]),
                   "r"(b[0]), "r"(b[1]));
}

// ---------------- GEMM config ----------------
#define MT 128
#define NT 64
#define BK 64                                   // k elems per chunk (128 B rows)
#define NCHUNK (EE / BK)                        // 16
#define OFF_AHI 0
#define OFF_ALO (MT * BK * 2)                   // 16384
#define OFF_BHI (2 * MT * BK * 2)               // 32768
#define OFF_BLO (2 * MT * BK * 2 + NT * BK * 2) // 40960
#define STAGE_BYTES (2 * MT * BK * 2 + 2 * NT * BK * 2)  // 49152
#define DSM_BYTES (2 * STAGE_BYTES)             // 98304 per CTA (2 CTAs/SM)

// ---------------- prepass: split enc into fp16 hi + scaled lo ----------------
__global__ void __launch_bounds__(256) split_enc_kernel(const float* __restrict__ A)
{
    size_t i = ((size_t)blockIdx.x * 256 + threadIdx.x) * 4;
    float4 v = *(const float4*)(A + i);
    __half h0 = __float2half_rn(v.x);
    __half h1 = __float2half_rn(v.y);
    __half h2 = __float2half_rn(v.z);
    __half h3 = __float2half_rn(v.w);
    __half l0 = __float2half_rn((v.x - __half2float(h0)) * LO_SCALE);
    __half l1 = __float2half_rn((v.y - __half2float(h1)) * LO_SCALE);
    __half l2 = __float2half_rn((v.z - __half2float(h2)) * LO_SCALE);
    __half l3 = __float2half_rn((v.w - __half2float(h3)) * LO_SCALE);
    __half2 hp0 = __halves2half2(h0, h1);
    __half2 hp1 = __halves2half2(h2, h3);
    __half2 lp0 = __halves2half2(l0, l1);
    __half2 lp1 = __halves2half2(l2, l3);
    *(uint2*)(g_Ahi + i) = make_uint2(*(uint32_t*)&hp0, *(uint32_t*)&hp1);
    *(uint2*)(g_Alo + i) = make_uint2(*(uint32_t*)&lp0, *(uint32_t*)&lp1);
}

// ---------------- prepass: transpose + split W -> Wt[n][k] fp16 hi + scaled lo ----------------
__global__ void __launch_bounds__(256) splitW_kernel(const float* __restrict__ W)
{
    __shared__ float tile[32][33];
    int n0 = blockIdx.x * 32, k0 = blockIdx.y * 32;
    int tx = threadIdx.x & 31, ty = threadIdx.x >> 5;  // 32 x 8
#pragma unroll
    for (int r = 0; r < 4; r++)
        tile[ty + 8 * r][tx] = W[(size_t)(k0 + ty + 8 * r) * EE + n0 + tx];
    __syncthreads();
#pragma unroll
    for (int r = 0; r < 4; r++) {
        int ny = ty + 8 * r;
        float v = tile[tx][ny];
        __half h = __float2half_rn(v);
        __half l = __float2half_rn((v - __half2float(h)) * LO_SCALE);
        size_t o = (size_t)(n0 + ny) * EE + k0 + tx;
        g_Bhi[o] = h;
        g_Blo[o] = l;
    }
}

__global__ void __launch_bounds__(256) zero_scores_kernel()
{
    g_scores[blockIdx.x * 256 + threadIdx.x] = 0.0f;
}

// ---------------- fused GEMM + bias + tanh + scores ----------------
__device__ __forceinline__ void load_chunk(int c, uint32_t sm0, size_t m0, int n0, int tid)
{
    uint32_t sb = sm0 + (uint32_t)(c & 1) * STAGE_BYTES;
    int k0 = c * BK;
    const __half* Ahi = g_Ahi + m0 * EE + k0;
    const __half* Alo = g_Alo + m0 * EE + k0;
    const __half* Bhi = g_Bhi + (size_t)n0 * EE + k0;
    const __half* Blo = g_Blo + (size_t)n0 * EE + k0;
#pragma unroll
    for (int i = 0; i < 4; i++) {           // A: 128 rows x 8 granules(16B)
        int idx = tid + i * 256;
        int row = idx >> 3, j = idx & 7;
        uint32_t d = sb + (uint32_t)(row * 128 + ((j ^ (row & 7)) << 4));
        const size_t go = (size_t)row * EE + j * 8;
        cpasync16(d + OFF_AHI, Ahi + go);
        cpasync16(d + OFF_ALO, Alo + go);
    }
#pragma unroll
    for (int i = 0; i < 2; i++) {           // B: 64 rows x 8 granules(16B)
        int idx = tid + i * 256;
        int row = idx >> 3, j = idx & 7;
        uint32_t d = sb + (uint32_t)(row * 128 + ((j ^ (row & 7)) << 4));
        const size_t go = (size_t)row * EE + j * 8;
        cpasync16(d + OFF_BHI, Bhi + go);
        cpasync16(d + OFF_BLO, Blo + go);
    }
    asm volatile("cp.async.commit_group;" ::: "memory");
}

__device__ __forceinline__ uint32_t a_frag_addr(uint32_t base, int row0, int t, int lane) {
    int r = row0 + (lane & 15);
    int j = t * 2 + (lane >> 4);
    return base + (uint32_t)(r * 128 + ((j ^ (r & 7)) << 4));
}
__device__ __forceinline__ uint32_t b_frag_addr(uint32_t base, int n0, int t, int lane) {
    int r = n0 + (lane & 7) + ((lane & 16) >> 1);
    int j = t * 2 + ((lane >> 3) & 1);
    return base + (uint32_t)(r * 128 + ((j ^ (r & 7)) << 4));
}

__global__ void __launch_bounds__(256, 2) gemm_hmma_kernel(
    const float* __restrict__ ctx,
    const float* __restrict__ bias)
{
    extern __shared__ __align__(1024) char dsm_raw[];
    uint32_t sm0 = smem_u32(dsm_raw);

    __shared__ float s_bias[NT];
    __shared__ float s_ctx[NT];

    const int tid = threadIdx.x;
    const int wid = tid >> 5, lane = tid & 31;
    const int warp_m = wid & 3;              // 0..3 (32-row slabs)
    const int warp_n = wid >> 2;             // 0..1 (32-col slabs)
    const int n0c = blockIdx.x * NT;
    const size_t m0 = (size_t)blockIdx.y * MT;
    const int bidx = (int)(m0 / TT);

    if (tid < NT) {
        s_bias[tid] = bias[n0c + tid];
        s_ctx[tid]  = ctx[bidx * EE + n0c + tid];
    }

    float acc[2][4][4];                      // main term, fp32
    uint32_t ach[2][4][2];                   // correction terms, fp16x2 (x 2^11)
#pragma unroll
    for (int mi = 0; mi < 2; mi++)
#pragma unroll
        for (int ni = 0; ni < 4; ni++) {
#pragma unroll
            for (int e = 0; e < 4; e++) acc[mi][ni][e] = 0.0f;
            ach[mi][ni][0] = 0u;
            ach[mi][ni][1] = 0u;
        }

    load_chunk(0, sm0, m0, n0c, tid);

    for (int c = 0; c < NCHUNK; c++) {
        asm volatile("cp.async.wait_group 0;" ::: "memory");
        __syncthreads();
        // prefetch next chunk into the buffer everyone just finished reading
        if (c + 1 < NCHUNK) load_chunk(c + 1, sm0, m0, n0c, tid);

        const uint32_t sb   = sm0 + (uint32_t)(c & 1) * STAGE_BYTES;
        const uint32_t sAhi = sb + OFF_AHI;
        const uint32_t sAlo = sb + OFF_ALO;
        const uint32_t sBhi = sb + OFF_BHI;
        const uint32_t sBlo = sb + OFF_BLO;

#pragma unroll
        for (int t = 0; t < 4; t++) {       // 4 k16 steps per BK=64
            uint32_t bh[2][4], bl[2][4], af[2][4], al[2][4];
#pragma unroll
            for (int np = 0; np < 2; np++) {
                ldsm4(bh[np], b_frag_addr(sBhi, warp_n * 32 + np * 16, t, lane));
                ldsm4(bl[np], b_frag_addr(sBlo, warp_n * 32 + np * 16, t, lane));
            }
#pragma unroll
            for (int mi = 0; mi < 2; mi++) {
                ldsm4(af[mi], a_frag_addr(sAhi, warp_m * 32 + mi * 16, t, lane));
                ldsm4(al[mi], a_frag_addr(sAlo, warp_m * 32 + mi * 16, t, lane));
            }
            // Bank 1: all 8 main MMAs (independent acc registers)
#pragma unroll
            for (int mi = 0; mi < 2; mi++)
#pragma unroll
                for (int ni = 0; ni < 4; ni++)
                    mma16816(acc[mi][ni], af[mi], &bh[ni >> 1][(ni & 1) * 2]);
            // Bank 2: all 8 Ahi*Blo corrections (first write of each ach this t)
#pragma unroll
            for (int mi = 0; mi < 2; mi++)
#pragma unroll
                for (int ni = 0; ni < 4; ni++)
                    mma16816h(ach[mi][ni], af[mi], &bl[ni >> 1][(ni & 1) * 2]);
            // Bank 3: all 8 Alo*Bhi corrections — each reuses ach[mi][ni] with
            // 7 independent MMAs issued since its previous write
#pragma unroll
            for (int mi = 0; mi < 2; mi++)
#pragma unroll
                for (int ni = 0; ni < 4; ni++)
                    mma16816h(ach[mi][ni], al[mi], &bh[ni >> 1][(ni & 1) * 2]);
        }
    }

    // epilogue: main + 2^-11 * corrections + bias, tanh, fp16 ht store, fused scores
    const int lr = lane >> 2;               // 0..7
    const int lc = (lane & 3) * 2;
    const int tbase = (int)(m0 % TT) + warp_m * 32;
#pragma unroll
    for (int mi = 0; mi < 2; mi++) {
        const size_t row0 = m0 + (size_t)(warp_m * 32 + mi * 16 + lr);
        float rs0 = 0.0f, rs1 = 0.0f;
#pragma unroll
        for (int ni = 0; ni < 4; ni++) {
            const int col = warp_n * 32 + ni * 8 + lc;
            const float b0 = s_bias[col], b1 = s_bias[col + 1];
            const float c0 = s_ctx[col],  c1 = s_ctx[col + 1];
            float2 cr0 = __half22float2(*(__half2*)&ach[mi][ni][0]);
            float2 cr1 = __half22float2(*(__half2*)&ach[mi][ni][1]);
            float2 v0, v1;
            v0.x = tanhf(acc[mi][ni][0] + LO_INV * cr0.x + b0);
            v0.y = tanhf(acc[mi][ni][1] + LO_INV * cr0.y + b1);
            v1.x = tanhf(acc[mi][ni][2] + LO_INV * cr1.x + b0);
            v1.y = tanhf(acc[mi][ni][3] + LO_INV * cr1.y + b1);
            *(__half2*)(g_ht + row0 * EE + n0c + col) = __float22half2_rn(v0);
            *(__half2*)(g_ht + (row0 + 8) * EE + n0c + col) = __float22half2_rn(v1);
            rs0 += v0.x * c0 + v0.y * c1;
            rs1 += v1.x * c0 + v1.y * c1;
        }
        rs0 += __shfl_xor_sync(0xffffffffu, rs0, 1);
        rs0 += __shfl_xor_sync(0xffffffffu, rs0, 2);
        rs1 += __shfl_xor_sync(0xffffffffu, rs1, 1);
        rs1 += __shfl_xor_sync(0xffffffffu, rs1, 2);
        if ((lane & 3) == 0) {
            atomicAdd(&g_scores[bidx * TT + tbase + mi * 16 + lr], rs0);
            atomicAdd(&g_scores[bidx * TT + tbase + mi * 16 + lr + 8], rs1);
        }
    }
}

// ---------------- softmax / pool ----------------
__global__ void __launch_bounds__(256) softmax_kernel()
{
    __shared__ float red[256];
    const int b = blockIdx.x;
    const int tid = threadIdx.x;

    float v[8];
    float m = -1e30f;
#pragma unroll
    for (int i = 0; i < 8; i++) {
        v[i] = g_scores[b * TT + tid + i * 256];
        m = fmaxf(m, v[i]);
    }
    red[tid] = m;
    __syncthreads();
#pragma unroll
    for (int s = 128; s > 0; s >>= 1) {
        if (tid < s) red[tid] = fmaxf(red[tid], red[tid + s]);
        __syncthreads();
    }
    const float mx = red[0];
    __syncthreads();

    float sum = 0.0f;
#pragma unroll
    for (int i = 0; i < 8; i++) {
        v[i] = expf(v[i] - mx);
        sum += v[i];
    }
    red[tid] = sum;
    __syncthreads();
#pragma unroll
    for (int s = 128; s > 0; s >>= 1) {
        if (tid < s) red[tid] += red[tid + s];
        __syncthreads();
    }
    const float inv = 1.0f / red[0];
#pragma unroll
    for (int i = 0; i < 8; i++)
        g_at[b * TT + tid + i * 256] = v[i] * inv;
}

// out[b][e0..e0+1] += sum_t at * ht ; ht fp16, 2 cols per thread
__global__ void __launch_bounds__(256) pool_kernel(float* __restrict__ out)
{
    __shared__ float ats[256];
    const int b = blockIdx.z;
    const int e = (blockIdx.x * 256 + threadIdx.x) * 2;
    const int t0 = blockIdx.y * 256;

    ats[threadIdx.x] = g_at[b * TT + t0 + threadIdx.x];
    __syncthreads();

    const __half2* hp = (const __half2*)(g_ht + ((size_t)(b * TT + t0)) * EE + e);
    float ax = 0.0f, ay = 0.0f;
#pragma unroll 8
    for (int i = 0; i < 256; i++) {
        float2 h = __half22float2(hp[(size_t)i * (EE / 2)]);
        ax += ats[i] * h.x;
        ay += ats[i] * h.y;
    }
    atomicAdd(&out[b * EE + e], ax);
    atomicAdd(&out[b * EE + e + 1], ay);
}

// ---------------- launch ----------------
extern "C" void kernel_launch(void* const* d_in, const int* in_sizes, int n_in,
                              void* d_out, int out_size)
{
    const float* enc  = (const float*)d_in[0];   // (B, T, E)
    const float* ctx  = (const float*)d_in[1];   // (B, E)
    const float* Wm   = (const float*)d_in[2];   // (E, E)
    const float* bias = (const float*)d_in[3];   // (1, E)
    float* out = (float*)d_out;                  // (B, E)

    cudaFuncSetAttribute(gemm_hmma_kernel,
                         cudaFuncAttributeMaxDynamicSharedMemorySize, DSM_BYTES);

    cudaMemsetAsync(out, 0, sizeof(float) * BB * EE);

    zero_scores_kernel<<<MTOT / 256, 256>>>();
    split_enc_kernel<<<(size_t)MTOT * EE / 1024, 256>>>(enc);
    splitW_kernel<<<dim3(EE / 32, EE / 32), 256>>>(Wm);
    gemm_hmma_kernel<<<dim3(EE / NT, MTOT / MT), 256, DSM_BYTES>>>(ctx, bias);
    softmax_kernel<<<BB, 256>>>();
    pool_kernel<<<dim3(EE / 512, TT / 256, BB), 256>>>(out);
}

// round 15
// speedup vs baseline: 1.3355x; 1.0005x over previous
#include <cuda_runtime.h>
#include <cuda_fp16.h>
#include <math.h>
#include <stdint.h>

#define BB 32
#define TT 2048
#define EE 1024
#define MTOT (BB * TT)   // 65536

// lo-parts are pre-scaled by 2^11 at split time; undone in the epilogue
#define LO_SCALE 2048.0f
#define LO_INV   (1.0f / 2048.0f)

// ---------------- device scratch ----------------
__device__ __half g_ht[(size_t)MTOT * EE];        // 128 MB, tanh(enc@W+b) fp16
__device__ float g_scores[MTOT];
__device__ __half g_Ahi[(size_t)MTOT * EE];       // 128 MB
__device__ __half g_Alo[(size_t)MTOT * EE];       // 128 MB (x 2^11)
__device__ __half g_Bhi[(size_t)EE * EE];         // Wt hi (N,K)
__device__ __half g_Blo[(size_t)EE * EE];         // Wt lo (N,K) (x 2^11)

// ---------------- helpers ----------------
__device__ __forceinline__ uint32_t smem_u32(const void* p) {
    uint32_t a;
    asm("{ .reg .u64 t; cvta.to.shared.u64 t, %1; cvt.u32.u64 %0, t; }"
        : "=r"(a) : "l"(p));
    return a;
}

__device__ __forceinline__ void cpasync16(uint32_t smem_dst, const void* gptr) {
    asm volatile("cp.async.cg.shared.global [%0], [%1], 16;"
                 :: "r"(smem_dst), "l"(gptr) : "memory");
}

__device__ __forceinline__ void ldsm4(uint32_t* r, uint32_t addr) {
    asm volatile("ldmatrix.sync.aligned.m8n8.x4.shared.b16 {%0,%1,%2,%3}, [%4];"
                 : "=r"(r[0]), "=r"(r[1]), "=r"(r[2]), "=r"(r[3]) : "r"(addr));
}

// fp32-accumulator fp16 MMA (main term)
__device__ __forceinline__ void mma16816(float* c, const uint32_t* a, const uint32_t* b) {
    asm volatile("mma.sync.aligned.m16n8k16.row.col.f32.f16.f16.f32 "
                 "{%0,%1,%2,%3}, {%4,%5,%6,%7}, {%8,%9}, {%0,%1,%2,%3};"
                 : "+f"(c[0]), "+f"(c[1]), "+f"(c[2]), "+f"(c[3])
                 : "r"(a[0]), "r"(a[1]), "r"(a[2]), "r"(a[3]),
                   "r"(b[0]), "r"(b[1]));
}

// fp16-accumulator fp16 MMA (correction terms)
__device__ __forceinline__ void mma16816h(uint32_t* c, const uint32_t* a, const uint32_t* b) {
    asm volatile("mma.sync.aligned.m16n8k16.row.col.f16.f16.f16.f16 "
                 "{%0,%1}, {%2,%3,%4,%5}, {%6,%7}, {%0,%1};"
                 : "+r"(c[0]), "+r"(c[1])
                 : "r"(a[0]), "r"(a[1]), "r"(a[2]), "r"(a[3]),
                   "r"(b[0]), "r"(b[1]));
}

// ---------------- GEMM config ----------------
#define MT 128
#define NT 64
#define BK 64                                   // k elems per chunk (128 B rows)
#define NCHUNK (EE / BK)                        // 16
#define OFF_AHI 0
#define OFF_ALO (MT * BK * 2)                   // 16384
#define OFF_BHI (2 * MT * BK * 2)               // 32768
#define OFF_BLO (2 * MT * BK * 2 + NT * BK * 2) // 40960
#define STAGE_BYTES (2 * MT * BK * 2 + 2 * NT * BK * 2)  // 49152
#define DSM_BYTES (2 * STAGE_BYTES)             // 98304 per CTA (2 CTAs/SM)

// ---------------- prepass: split enc into fp16 hi + scaled lo (+ zero scores) --
__global__ void __launch_bounds__(256) split_enc_kernel(const float* __restrict__ A)
{
    // fold scores zeroing into the first 256 blocks (MTOT/256 = 256)
    if (blockIdx.x < MTOT / 256)
        g_scores[blockIdx.x * 256 + threadIdx.x] = 0.0f;

    size_t i = ((size_t)blockIdx.x * 256 + threadIdx.x) * 4;
    float4 v = *(const float4*)(A + i);
    __half h0 = __float2half_rn(v.x);
    __half h1 = __float2half_rn(v.y);
    __half h2 = __float2half_rn(v.z);
    __half h3 = __float2half_rn(v.w);
    __half l0 = __float2half_rn((v.x - __half2float(h0)) * LO_SCALE);
    __half l1 = __float2half_rn((v.y - __half2float(h1)) * LO_SCALE);
    __half l2 = __float2half_rn((v.z - __half2float(h2)) * LO_SCALE);
    __half l3 = __float2half_rn((v.w - __half2float(h3)) * LO_SCALE);
    __half2 hp0 = __halves2half2(h0, h1);
    __half2 hp1 = __halves2half2(h2, h3);
    __half2 lp0 = __halves2half2(l0, l1);
    __half2 lp1 = __halves2half2(l2, l3);
    *(uint2*)(g_Ahi + i) = make_uint2(*(uint32_t*)&hp0, *(uint32_t*)&hp1);
    *(uint2*)(g_Alo + i) = make_uint2(*(uint32_t*)&lp0, *(uint32_t*)&lp1);
}

// ---------------- prepass: transpose + split W -> Wt[n][k] fp16 hi + scaled lo --
__global__ void __launch_bounds__(256) splitW_kernel(const float* __restrict__ W)
{
    __shared__ float tile[32][33];
    int n0 = blockIdx.x * 32, k0 = blockIdx.y * 32;
    int tx = threadIdx.x & 31, ty = threadIdx.x >> 5;  // 32 x 8
#pragma unroll
    for (int r = 0; r < 4; r++)
        tile[ty + 8 * r][tx] = W[(size_t)(k0 + ty + 8 * r) * EE + n0 + tx];
    __syncthreads();
#pragma unroll
    for (int r = 0; r < 4; r++) {
        int ny = ty + 8 * r;
        float v = tile[tx][ny];
        __half h = __float2half_rn(v);
        __half l = __float2half_rn((v - __half2float(h)) * LO_SCALE);
        size_t o = (size_t)(n0 + ny) * EE + k0 + tx;
        g_Bhi[o] = h;
        g_Blo[o] = l;
    }
}

// ---------------- fused GEMM + bias + tanh + scores ----------------
__device__ __forceinline__ void load_chunk(int c, uint32_t sm0, size_t m0, int n0, int tid)
{
    uint32_t sb = sm0 + (uint32_t)(c & 1) * STAGE_BYTES;
    int k0 = c * BK;
    const __half* Ahi = g_Ahi + m0 * EE + k0;
    const __half* Alo = g_Alo + m0 * EE + k0;
    const __half* Bhi = g_Bhi + (size_t)n0 * EE + k0;
    const __half* Blo = g_Blo + (size_t)n0 * EE + k0;
#pragma unroll
    for (int i = 0; i < 4; i++) {           // A: 128 rows x 8 granules(16B)
        int idx = tid + i * 256;
        int row = idx >> 3, j = idx & 7;
        uint32_t d = sb + (uint32_t)(row * 128 + ((j ^ (row & 7)) << 4));
        const size_t go = (size_t)row * EE + j * 8;
        cpasync16(d + OFF_AHI, Ahi + go);
        cpasync16(d + OFF_ALO, Alo + go);
    }
#pragma unroll
    for (int i = 0; i < 2; i++) {           // B: 64 rows x 8 granules(16B)
        int idx = tid + i * 256;
        int row = idx >> 3, j = idx & 7;
        uint32_t d = sb + (uint32_t)(row * 128 + ((j ^ (row & 7)) << 4));
        const size_t go = (size_t)row * EE + j * 8;
        cpasync16(d + OFF_BHI, Bhi + go);
        cpasync16(d + OFF_BLO, Blo + go);
    }
    asm volatile("cp.async.commit_group;" ::: "memory");
}

__device__ __forceinline__ uint32_t a_frag_addr(uint32_t base, int row0, int t, int lane) {
    int r = row0 + (lane & 15);
    int j = t * 2 + (lane >> 4);
    return base + (uint32_t)(r * 128 + ((j ^ (r & 7)) << 4));
}
__device__ __forceinline__ uint32_t b_frag_addr(uint32_t base, int n0, int t, int lane) {
    int r = n0 + (lane & 7) + ((lane & 16) >> 1);
    int j = t * 2 + ((lane >> 3) & 1);
    return base + (uint32_t)(r * 128 + ((j ^ (r & 7)) << 4));
}

__global__ void __launch_bounds__(256, 2) gemm_hmma_kernel(
    const float* __restrict__ ctx,
    const float* __restrict__ bias)
{
    extern __shared__ __align__(1024) char dsm_raw[];
    uint32_t sm0 = smem_u32(dsm_raw);

    __shared__ float s_bias[NT];
    __shared__ float s_ctx[NT];

    const int tid = threadIdx.x;
    const int wid = tid >> 5, lane = tid & 31;
    const int warp_m = wid & 3;              // 0..3 (32-row slabs)
    const int warp_n = wid >> 2;             // 0..1 (32-col slabs)
    const int n0c = blockIdx.x * NT;
    const size_t m0 = (size_t)blockIdx.y * MT;
    const int bidx = (int)(m0 / TT);

    if (tid < NT) {
        s_bias[tid] = bias[n0c + tid];
        s_ctx[tid]  = ctx[bidx * EE + n0c + tid];
    }

    float acc[2][4][4];                      // main term, fp32
    uint32_t ach[2][4][2];                   // correction terms, fp16x2 (x 2^11)
#pragma unroll
    for (int mi = 0; mi < 2; mi++)
#pragma unroll
        for (int ni = 0; ni < 4; ni++) {
#pragma unroll
            for (int e = 0; e < 4; e++) acc[mi][ni][e] = 0.0f;
            ach[mi][ni][0] = 0u;
            ach[mi][ni][1] = 0u;
        }

    load_chunk(0, sm0, m0, n0c, tid);

    for (int c = 0; c < NCHUNK; c++) {
        asm volatile("cp.async.wait_group 0;" ::: "memory");
        __syncthreads();
        // prefetch next chunk into the buffer everyone just finished reading
        if (c + 1 < NCHUNK) load_chunk(c + 1, sm0, m0, n0c, tid);

        const uint32_t sb   = sm0 + (uint32_t)(c & 1) * STAGE_BYTES;
        const uint32_t sAhi = sb + OFF_AHI;
        const uint32_t sAlo = sb + OFF_ALO;
        const uint32_t sBhi = sb + OFF_BHI;
        const uint32_t sBlo = sb + OFF_BLO;

#pragma unroll
        for (int t = 0; t < 4; t++) {       // 4 k16 steps per BK=64
            uint32_t bh[2][4], bl[2][4], af[2][4], al[2][4];
#pragma unroll
            for (int np = 0; np < 2; np++) {
                ldsm4(bh[np], b_frag_addr(sBhi, warp_n * 32 + np * 16, t, lane));
                ldsm4(bl[np], b_frag_addr(sBlo, warp_n * 32 + np * 16, t, lane));
            }
#pragma unroll
            for (int mi = 0; mi < 2; mi++) {
                ldsm4(af[mi], a_frag_addr(sAhi, warp_m * 32 + mi * 16, t, lane));
                ldsm4(al[mi], a_frag_addr(sAlo, warp_m * 32 + mi * 16, t, lane));
            }
#pragma unroll
            for (int mi = 0; mi < 2; mi++)
#pragma unroll
                for (int ni = 0; ni < 4; ni++)
                    mma16816(acc[mi][ni], af[mi], &bh[ni >> 1][(ni & 1) * 2]);
#pragma unroll
            for (int mi = 0; mi < 2; mi++)
#pragma unroll
                for (int ni = 0; ni < 4; ni++)
                    mma16816h(ach[mi][ni], af[mi], &bl[ni >> 1][(ni & 1) * 2]);
#pragma unroll
            for (int mi = 0; mi < 2; mi++)
#pragma unroll
                for (int ni = 0; ni < 4; ni++)
                    mma16816h(ach[mi][ni], al[mi], &bh[ni >> 1][(ni & 1) * 2]);
        }
    }

    // epilogue: main + 2^-11 * corrections + bias, tanh, fp16 ht store, fused scores
    const int lr = lane >> 2;               // 0..7
    const int lc = (lane & 3) * 2;
    const int tbase = (int)(m0 % TT) + warp_m * 32;
#pragma unroll
    for (int mi = 0; mi < 2; mi++) {
        const size_t row0 = m0 + (size_t)(warp_m * 32 + mi * 16 + lr);
        float rs0 = 0.0f, rs1 = 0.0f;
#pragma unroll
        for (int ni = 0; ni < 4; ni++) {
            const int col = warp_n * 32 + ni * 8 + lc;
            const float b0 = s_bias[col], b1 = s_bias[col + 1];
            const float c0 = s_ctx[col],  c1 = s_ctx[col + 1];
            float2 cr0 = __half22float2(*(__half2*)&ach[mi][ni][0]);
            float2 cr1 = __half22float2(*(__half2*)&ach[mi][ni][1]);
            float2 v0, v1;
            v0.x = tanhf(acc[mi][ni][0] + LO_INV * cr0.x + b0);
            v0.y = tanhf(acc[mi][ni][1] + LO_INV * cr0.y + b1);
            v1.x = tanhf(acc[mi][ni][2] + LO_INV * cr1.x + b0);
            v1.y = tanhf(acc[mi][ni][3] + LO_INV * cr1.y + b1);
            *(__half2*)(g_ht + row0 * EE + n0c + col) = __float22half2_rn(v0);
            *(__half2*)(g_ht + (row0 + 8) * EE + n0c + col) = __float22half2_rn(v1);
            rs0 += v0.x * c0 + v0.y * c1;
            rs1 += v1.x * c0 + v1.y * c1;
        }
        rs0 += __shfl_xor_sync(0xffffffffu, rs0, 1);
        rs0 += __shfl_xor_sync(0xffffffffu, rs0, 2);
        rs1 += __shfl_xor_sync(0xffffffffu, rs1, 1);
        rs1 += __shfl_xor_sync(0xffffffffu, rs1, 2);
        if ((lane & 3) == 0) {
            atomicAdd(&g_scores[bidx * TT + tbase + mi * 16 + lr], rs0);
            atomicAdd(&g_scores[bidx * TT + tbase + mi * 16 + lr + 8], rs1);
        }
    }
}

// ---------------- fused softmax + pool ----------------
// Each block recomputes the softmax normalizers (max, sum) over all TT scores
// of its batch (8 KB read, trivial vs the 128 MB ht read), builds its local 256
// at values, then accumulates out[b][e0..e0+1] over its 256 timesteps.
__global__ void __launch_bounds__(256) pool_kernel(float* __restrict__ out)
{
    __shared__ float red[256];
    __shared__ float ats[256];
    const int b = blockIdx.z;
    const int tid = threadIdx.x;
    const int e = (blockIdx.x * 256 + tid) * 2;
    const int t0 = blockIdx.y * 256;

    // softmax normalizers over the full row of scores
    float v[8];
    float m = -1e30f;
#pragma unroll
    for (int i = 0; i < 8; i++) {
        v[i] = g_scores[b * TT + tid + i * 256];
        m = fmaxf(m, v[i]);
    }
    red[tid] = m;
    __syncthreads();
#pragma unroll
    for (int s = 128; s > 0; s >>= 1) {
        if (tid < s) red[tid] = fmaxf(red[tid], red[tid + s]);
        __syncthreads();
    }
    const float mx = red[0];
    __syncthreads();

    float sum = 0.0f;
#pragma unroll
    for (int i = 0; i < 8; i++)
        sum += expf(v[i] - mx);
    red[tid] = sum;
    __syncthreads();
#pragma unroll
    for (int s = 128; s > 0; s >>= 1) {
        if (tid < s) red[tid] += red[tid + s];
        __syncthreads();
    }
    const float inv = 1.0f / red[0];

    // local at values for this block's 256 timesteps
    ats[tid] = expf(g_scores[b * TT + t0 + tid] - mx) * inv;
    __syncthreads();

    const __half2* hp = (const __half2*)(g_ht + ((size_t)(b * TT + t0)) * EE + e);
    float ax = 0.0f, ay = 0.0f;
#pragma unroll 8
    for (int i = 0; i < 256; i++) {
        float2 h = __half22float2(hp[(size_t)i * (EE / 2)]);
        ax += ats[i] * h.x;
        ay += ats[i] * h.y;
    }
    atomicAdd(&out[b * EE + e], ax);
    atomicAdd(&out[b * EE + e + 1], ay);
}

// ---------------- launch ----------------
extern "C" void kernel_launch(void* const* d_in, const int* in_sizes, int n_in,
                              void* d_out, int out_size)
{
    const float* enc  = (const float*)d_in[0];   // (B, T, E)
    const float* ctx  = (const float*)d_in[1];   // (B, E)
    const float* Wm   = (const float*)d_in[2];   // (E, E)
    const float* bias = (const float*)d_in[3];   // (1, E)
    float* out = (float*)d_out;                  // (B, E)

    cudaFuncSetAttribute(gemm_hmma_kernel,
                         cudaFuncAttributeMaxDynamicSharedMemorySize, DSM_BYTES);

    cudaMemsetAsync(out, 0, sizeof(float) * BB * EE);

    split_enc_kernel<<<(size_t)MTOT * EE / 1024, 256>>>(enc);
    splitW_kernel<<<dim3(EE / 32, EE / 32), 256>>>(Wm);
    gemm_hmma_kernel<<<dim3(EE / NT, MTOT / MT), 256, DSM_BYTES>>>(ctx, bias);
    pool_kernel<<<dim3(EE / 512, TT / 256, BB), 256>>>(out);
}

// round 16
// speedup vs baseline: 1.3397x; 1.0031x over previous
#include <cuda_runtime.h>
#include <cuda_fp16.h>
#include <math.h>
#include <stdint.h>

#define BB 32
#define TT 2048
#define EE 1024
#define MTOT (BB * TT)   // 65536

// lo-parts are pre-scaled by 2^11 at split time; undone in the epilogue
#define LO_SCALE 2048.0f
#define LO_INV   (1.0f / 2048.0f)

// ---------------- device scratch ----------------
__device__ __half g_ht[(size_t)MTOT * EE];        // 128 MB, tanh(enc@W+b) fp16
__device__ float g_scores[MTOT];
__device__ __half g_Ahi[(size_t)MTOT * EE];       // 128 MB
__device__ __half g_Alo[(size_t)MTOT * EE];       // 128 MB (x 2^11)
__device__ __half g_Bhi[(size_t)EE * EE];         // Wt hi (N,K)
__device__ __half g_Blo[(size_t)EE * EE];         // Wt lo (N,K) (x 2^11)

// ---------------- helpers ----------------
__device__ __forceinline__ uint32_t smem_u32(const void* p) {
    uint32_t a;
    asm("{ .reg .u64 t; cvta.to.shared.u64 t, %1; cvt.u32.u64 %0, t; }"
        : "=r"(a) : "l"(p));
    return a;
}

__device__ __forceinline__ void cpasync16(uint32_t smem_dst, const void* gptr) {
    asm volatile("cp.async.cg.shared.global [%0], [%1], 16;"
                 :: "r"(smem_dst), "l"(gptr) : "memory");
}

__device__ __forceinline__ void ldsm4(uint32_t* r, uint32_t addr) {
    asm volatile("ldmatrix.sync.aligned.m8n8.x4.shared.b16 {%0,%1,%2,%3}, [%4];"
                 : "=r"(r[0]), "=r"(r[1]), "=r"(r[2]), "=r"(r[3]) : "r"(addr));
}

// fp32-accumulator fp16 MMA (main term)
__device__ __forceinline__ void mma16816(float* c, const uint32_t* a, const uint32_t* b) {
    asm volatile("mma.sync.aligned.m16n8k16.row.col.f32.f16.f16.f32 "
                 "{%0,%1,%2,%3}, {%4,%5,%6,%7}, {%8,%9}, {%0,%1,%2,%3};"
                 : "+f"(c[0]), "+f"(c[1]), "+f"(c[2]), "+f"(c[3])
                 : "r"(a[0]), "r"(a[1]), "r"(a[2]), "r"(a[3]),
                   "r"(b[0]), "r"(b[1]));
}

// fp16-accumulator fp16 MMA (correction terms)
__device__ __forceinline__ void mma16816h(uint32_t* c, const uint32_t* a, const uint32_t* b) {
    asm volatile("mma.sync.aligned.m16n8k16.row.col.f16.f16.f16.f16 "
                 "{%0,%1}, {%2,%3,%4,%5}, {%6,%7}, {%0,%1};"
                 : "+r"(c[0]), "+r"(c[1])
                 : "r"(a[0]), "r"(a[1]), "r"(a[2]), "r"(a[3]),
                   "r"(b[0]), "r"(b[1]));
}

// ---------------- GEMM config ----------------
#define MT 128
#define NT 64
#define BK 64                                   // k elems per chunk (128 B rows)
#define NCHUNK (EE / BK)                        // 16
#define OFF_AHI 0
#define OFF_ALO (MT * BK * 2)                   // 16384
#define OFF_BHI (2 * MT * BK * 2)               // 32768
#define OFF_BLO (2 * MT * BK * 2 + NT * BK * 2) // 40960
#define STAGE_BYTES (2 * MT * BK * 2 + 2 * NT * BK * 2)  // 49152
#define DSM_BYTES (2 * STAGE_BYTES)             // 98304 per CTA (2 CTAs/SM)

// ---------------- prepass: split enc into fp16 hi + scaled lo (+ zero scores) --
__global__ void __launch_bounds__(256) split_enc_kernel(const float* __restrict__ A)
{
    // fold scores zeroing into the first 256 blocks (MTOT/256 = 256)
    if (blockIdx.x < MTOT / 256)
        g_scores[blockIdx.x * 256 + threadIdx.x] = 0.0f;

    size_t i = ((size_t)blockIdx.x * 256 + threadIdx.x) * 4;
    float4 v = *(const float4*)(A + i);
    __half h0 = __float2half_rn(v.x);
    __half h1 = __float2half_rn(v.y);
    __half h2 = __float2half_rn(v.z);
    __half h3 = __float2half_rn(v.w);
    __half l0 = __float2half_rn((v.x - __half2float(h0)) * LO_SCALE);
    __half l1 = __float2half_rn((v.y - __half2float(h1)) * LO_SCALE);
    __half l2 = __float2half_rn((v.z - __half2float(h2)) * LO_SCALE);
    __half l3 = __float2half_rn((v.w - __half2float(h3)) * LO_SCALE);
    __half2 hp0 = __halves2half2(h0, h1);
    __half2 hp1 = __halves2half2(h2, h3);
    __half2 lp0 = __halves2half2(l0, l1);
    __half2 lp1 = __halves2half2(l2, l3);
    *(uint2*)(g_Ahi + i) = make_uint2(*(uint32_t*)&hp0, *(uint32_t*)&hp1);
    *(uint2*)(g_Alo + i) = make_uint2(*(uint32_t*)&lp0, *(uint32_t*)&lp1);
}

// ---------------- prepass: transpose + split W -> Wt[n][k] fp16 hi + scaled lo --
__global__ void __launch_bounds__(256) splitW_kernel(const float* __restrict__ W)
{
    __shared__ float tile[32][33];
    int n0 = blockIdx.x * 32, k0 = blockIdx.y * 32;
    int tx = threadIdx.x & 31, ty = threadIdx.x >> 5;  // 32 x 8
#pragma unroll
    for (int r = 0; r < 4; r++)
        tile[ty + 8 * r][tx] = W[(size_t)(k0 + ty + 8 * r) * EE + n0 + tx];
    __syncthreads();
#pragma unroll
    for (int r = 0; r < 4; r++) {
        int ny = ty + 8 * r;
        float v = tile[tx][ny];
        __half h = __float2half_rn(v);
        __half l = __float2half_rn((v - __half2float(h)) * LO_SCALE);
        size_t o = (size_t)(n0 + ny) * EE + k0 + tx;
        g_Bhi[o] = h;
        g_Blo[o] = l;
    }
}

// ---------------- fused GEMM + bias + tanh + scores ----------------
__device__ __forceinline__ void load_chunk(int c, uint32_t sm0, size_t m0, int n0, int tid)
{
    uint32_t sb = sm0 + (uint32_t)(c & 1) * STAGE_BYTES;
    int k0 = c * BK;
    const __half* Ahi = g_Ahi + m0 * EE + k0;
    const __half* Alo = g_Alo + m0 * EE + k0;
    const __half* Bhi = g_Bhi + (size_t)n0 * EE + k0;
    const __half* Blo = g_Blo + (size_t)n0 * EE + k0;
#pragma unroll
    for (int i = 0; i < 4; i++) {           // A: 128 rows x 8 granules(16B)
        int idx = tid + i * 256;
        int row = idx >> 3, j = idx & 7;
        uint32_t d = sb + (uint32_t)(row * 128 + ((j ^ (row & 7)) << 4));
        const size_t go = (size_t)row * EE + j * 8;
        cpasync16(d + OFF_AHI, Ahi + go);
        cpasync16(d + OFF_ALO, Alo + go);
    }
#pragma unroll
    for (int i = 0; i < 2; i++) {           // B: 64 rows x 8 granules(16B)
        int idx = tid + i * 256;
        int row = idx >> 3, j = idx & 7;
        uint32_t d = sb + (uint32_t)(row * 128 + ((j ^ (row & 7)) << 4));
        const size_t go = (size_t)row * EE + j * 8;
        cpasync16(d + OFF_BHI, Bhi + go);
        cpasync16(d + OFF_BLO, Blo + go);
    }
    asm volatile("cp.async.commit_group;" ::: "memory");
}

__device__ __forceinline__ uint32_t a_frag_addr(uint32_t base, int row0, int t, int lane) {
    int r = row0 + (lane & 15);
    int j = t * 2 + (lane >> 4);
    return base + (uint32_t)(r * 128 + ((j ^ (r & 7)) << 4));
}
__device__ __forceinline__ uint32_t b_frag_addr(uint32_t base, int n0, int t, int lane) {
    int r = n0 + (lane & 7) + ((lane & 16) >> 1);
    int j = t * 2 + ((lane >> 3) & 1);
    return base + (uint32_t)(r * 128 + ((j ^ (r & 7)) << 4));
}

__global__ void __launch_bounds__(256, 2) gemm_hmma_kernel(
    const float* __restrict__ ctx,
    const float* __restrict__ bias)
{
    extern __shared__ __align__(1024) char dsm_raw[];
    uint32_t sm0 = smem_u32(dsm_raw);

    __shared__ float s_bias[NT];
    __shared__ float s_ctx[NT];

    const int tid = threadIdx.x;
    const int wid = tid >> 5, lane = tid & 31;
    const int warp_m = wid & 3;              // 0..3 (32-row slabs)
    const int warp_n = wid >> 2;             // 0..1 (32-col slabs)
    const int n0c = blockIdx.x * NT;
    const size_t m0 = (size_t)blockIdx.y * MT;
    const int bidx = (int)(m0 / TT);

    if (tid < NT) {
        s_bias[tid] = bias[n0c + tid];
        s_ctx[tid]  = ctx[bidx * EE + n0c + tid];
    }

    float acc[2][4][4];                      // main term, fp32
    uint32_t ach[2][4][2];                   // correction terms, fp16x2 (x 2^11)
#pragma unroll
    for (int mi = 0; mi < 2; mi++)
#pragma unroll
        for (int ni = 0; ni < 4; ni++) {
#pragma unroll
            for (int e = 0; e < 4; e++) acc[mi][ni][e] = 0.0f;
            ach[mi][ni][0] = 0u;
            ach[mi][ni][1] = 0u;
        }

    load_chunk(0, sm0, m0, n0c, tid);

    for (int c = 0; c < NCHUNK; c++) {
        asm volatile("cp.async.wait_group 0;" ::: "memory");
        __syncthreads();
        // prefetch next chunk into the buffer everyone just finished reading
        if (c + 1 < NCHUNK) load_chunk(c + 1, sm0, m0, n0c, tid);

        const uint32_t sb   = sm0 + (uint32_t)(c & 1) * STAGE_BYTES;
        const uint32_t sAhi = sb + OFF_AHI;
        const uint32_t sAlo = sb + OFF_ALO;
        const uint32_t sBhi = sb + OFF_BHI;
        const uint32_t sBlo = sb + OFF_BLO;

#pragma unroll
        for (int t = 0; t < 4; t++) {       // 4 k16 steps per BK=64
            uint32_t bh[2][4], bl[2][4], af[2][4], al[2][4];
#pragma unroll
            for (int np = 0; np < 2; np++) {
                ldsm4(bh[np], b_frag_addr(sBhi, warp_n * 32 + np * 16, t, lane));
                ldsm4(bl[np], b_frag_addr(sBlo, warp_n * 32 + np * 16, t, lane));
            }
#pragma unroll
            for (int mi = 0; mi < 2; mi++) {
                ldsm4(af[mi], a_frag_addr(sAhi, warp_m * 32 + mi * 16, t, lane));
                ldsm4(al[mi], a_frag_addr(sAlo, warp_m * 32 + mi * 16, t, lane));
            }
#pragma unroll
            for (int mi = 0; mi < 2; mi++)
#pragma unroll
                for (int ni = 0; ni < 4; ni++)
                    mma16816(acc[mi][ni], af[mi], &bh[ni >> 1][(ni & 1) * 2]);
#pragma unroll
            for (int mi = 0; mi < 2; mi++)
#pragma unroll
                for (int ni = 0; ni < 4; ni++)
                    mma16816h(ach[mi][ni], af[mi], &bl[ni >> 1][(ni & 1) * 2]);
#pragma unroll
            for (int mi = 0; mi < 2; mi++)
#pragma unroll
                for (int ni = 0; ni < 4; ni++)
                    mma16816h(ach[mi][ni], al[mi], &bh[ni >> 1][(ni & 1) * 2]);
        }
    }

    // epilogue: main + 2^-11 * corrections + bias, tanh, fp16 ht store, fused scores
    const int lr = lane >> 2;               // 0..7
    const int lc = (lane & 3) * 2;
    const int tbase = (int)(m0 % TT) + warp_m * 32;
#pragma unroll
    for (int mi = 0; mi < 2; mi++) {
        const size_t row0 = m0 + (size_t)(warp_m * 32 + mi * 16 + lr);
        float rs0 = 0.0f, rs1 = 0.0f;
#pragma unroll
        for (int ni = 0; ni < 4; ni++) {
            const int col = warp_n * 32 + ni * 8 + lc;
            const float b0 = s_bias[col], b1 = s_bias[col + 1];
            const float c0 = s_ctx[col],  c1 = s_ctx[col + 1];
            float2 cr0 = __half22float2(*(__half2*)&ach[mi][ni][0]);
            float2 cr1 = __half22float2(*(__half2*)&ach[mi][ni][1]);
            float2 v0, v1;
            v0.x = tanhf(acc[mi][ni][0] + LO_INV * cr0.x + b0);
            v0.y = tanhf(acc[mi][ni][1] + LO_INV * cr0.y + b1);
            v1.x = tanhf(acc[mi][ni][2] + LO_INV * cr1.x + b0);
            v1.y = tanhf(acc[mi][ni][3] + LO_INV * cr1.y + b1);
            *(__half2*)(g_ht + row0 * EE + n0c + col) = __float22half2_rn(v0);
            *(__half2*)(g_ht + (row0 + 8) * EE + n0c + col) = __float22half2_rn(v1);
            rs0 += v0.x * c0 + v0.y * c1;
            rs1 += v1.x * c0 + v1.y * c1;
        }
        rs0 += __shfl_xor_sync(0xffffffffu, rs0, 1);
        rs0 += __shfl_xor_sync(0xffffffffu, rs0, 2);
        rs1 += __shfl_xor_sync(0xffffffffu, rs1, 1);
        rs1 += __shfl_xor_sync(0xffffffffu, rs1, 2);
        if ((lane & 3) == 0) {
            atomicAdd(&g_scores[bidx * TT + tbase + mi * 16 + lr], rs0);
            atomicAdd(&g_scores[bidx * TT + tbase + mi * 16 + lr + 8], rs1);
        }
    }
}

// ---------------- fused softmax + pool ----------------
// Each block: recompute softmax normalizers over the batch's TT scores (8 KB),
// build at for its 128 timesteps, accumulate out[b][e0..e0+3].
// Each thread owns 4 columns (one uint2 = 8 B per row): a 256-thread block
// reads a FULL contiguous 2 KB ht row per timestep (perfect sectors, 2x MLP).
__global__ void __launch_bounds__(256) pool_kernel(float* __restrict__ out)
{
    __shared__ float red[256];
    __shared__ float ats[128];
    const int b = blockIdx.z;
    const int tid = threadIdx.x;
    const int e = tid * 4;                   // 4 half columns
    const int t0 = blockIdx.y * 128;

    // softmax normalizers over the full row of scores
    float v[8];
    float m = -1e30f;
#pragma unroll
    for (int i = 0; i < 8; i++) {
        v[i] = g_scores[b * TT + tid + i * 256];
        m = fmaxf(m, v[i]);
    }
    red[tid] = m;
    __syncthreads();
#pragma unroll
    for (int s = 128; s > 0; s >>= 1) {
        if (tid < s) red[tid] = fmaxf(red[tid], red[tid + s]);
        __syncthreads();
    }
    const float mx = red[0];
    __syncthreads();

    float sum = 0.0f;
#pragma unroll
    for (int i = 0; i < 8; i++)
        sum += expf(v[i] - mx);
    red[tid] = sum;
    __syncthreads();
#pragma unroll
    for (int s = 128; s > 0; s >>= 1) {
        if (tid < s) red[tid] += red[tid + s];
        __syncthreads();
    }
    const float inv = 1.0f / red[0];

    // local at values for this block's 128 timesteps
    if (tid < 128)
        ats[tid] = expf(g_scores[b * TT + t0 + tid] - mx) * inv;
    __syncthreads();

    const __half* hp0 = g_ht + ((size_t)(b * TT + t0)) * EE + e;
    float a0 = 0.0f, a1 = 0.0f, a2 = 0.0f, a3 = 0.0f;
#pragma unroll 8
    for (int i = 0; i < 128; i++) {
        uint2 u = *(const uint2*)(hp0 + (size_t)i * EE);
        float2 h0 = __half22float2(*(__half2*)&u.x);
        float2 h1 = __half22float2(*(__half2*)&u.y);
        const float w = ats[i];
        a0 += w * h0.x;
        a1 += w * h0.y;
        a2 += w * h1.x;
        a3 += w * h1.y;
    }
    atomicAdd(&out[b * EE + e + 0], a0);
    atomicAdd(&out[b * EE + e + 1], a1);
    atomicAdd(&out[b * EE + e + 2], a2);
    atomicAdd(&out[b * EE + e + 3], a3);
}

// ---------------- launch ----------------
extern "C" void kernel_launch(void* const* d_in, const int* in_sizes, int n_in,
                              void* d_out, int out_size)
{
    const float* enc  = (const float*)d_in[0];   // (B, T, E)
    const float* ctx  = (const float*)d_in[1];   // (B, E)
    const float* Wm   = (const float*)d_in[2];   // (E, E)
    const float* bias = (const float*)d_in[3];   // (1, E)
    float* out = (float*)d_out;                  // (B, E)

    cudaFuncSetAttribute(gemm_hmma_kernel,
                         cudaFuncAttributeMaxDynamicSharedMemorySize, DSM_BYTES);

    cudaMemsetAsync(out, 0, sizeof(float) * BB * EE);

    split_enc_kernel<<<(size_t)MTOT * EE / 1024, 256>>>(enc);
    splitW_kernel<<<dim3(EE / 32, EE / 32), 256>>>(Wm);
    gemm_hmma_kernel<<<dim3(EE / NT, MTOT / MT), 256, DSM_BYTES>>>(ctx, bias);
    pool_kernel<<<dim3(1, TT / 128, BB), 256>>>(out);
}